// round 2
// baseline (speedup 1.0000x reference)
#include <cuda_runtime.h>
#include <cuda_bf16.h>
#include <cstdint>

// Problem constants
#define Bn   4
#define Sn   96
#define Nn   512
#define Dn   8
#define Hn   64
#define G4   256          // 4*H
#define Fn   72           // D + H
#define OUTn 24

#define ROWS 16           // node rows per CTA
#define TPB  256          // 8 warps

// Dynamic smem layout (floats):
//   [0      , 8192 )  A-frag hi   (64 kc x 32 lanes x 4 regs)   } gsm (16x260) overlays
//   [8192   , 16384)  A-frag lo
//   [16384  , 17600)  ah  (16 rows x 76)
#define SM_AHI   0
#define SM_ALO   8192
#define SM_AH    16384
#define SMEM_FLOATS 17600
#define SMEM_BYTES  (SMEM_FLOATS * 4)

// Persistent device state
__device__ float d_hbuf[2][Bn * Nn * Hn];
__device__ float d_cbuf[Bn * Nn * Hn];
// Pre-split W fragments: [kk(9)][ntile(32)][lane(32)][b0h,b1h,b0l,b1l]
__device__ float d_Wfrag[9 * 32 * 32 * 4];

__device__ __forceinline__ unsigned f2tf(float f) {
    unsigned r;
    asm("cvt.rna.tf32.f32 %0, %1;" : "=r"(r) : "f"(f));
    return r;
}
__device__ __forceinline__ void splitf(float v, unsigned& hi, unsigned& lo) {
    hi = f2tf(v);
    lo = f2tf(v - __uint_as_float(hi));
}

__device__ __forceinline__ void mma_tf32(float c[4],
                                         unsigned a0, unsigned a1, unsigned a2, unsigned a3,
                                         unsigned b0, unsigned b1) {
    asm volatile(
        "mma.sync.aligned.m16n8k8.row.col.f32.tf32.tf32.f32 "
        "{%0,%1,%2,%3}, {%4,%5,%6,%7}, {%8,%9}, {%0,%1,%2,%3};\n"
        : "+f"(c[0]), "+f"(c[1]), "+f"(c[2]), "+f"(c[3])
        : "r"(a0), "r"(a1), "r"(a2), "r"(a3), "r"(b0), "r"(b1));
}

__device__ __forceinline__ float sigmoidf_fast(float x) { return 1.0f / (1.0f + __expf(-x)); }
__device__ __forceinline__ float tanhf_fast(float x)    { return 1.0f - 2.0f / (__expf(2.0f * x) + 1.0f); }

// ---------------------------------------------------------------------------
// init: copy h0/c0 into ping-pong buffers; pre-split W = [Wx;Wh] into mma
// B-fragment layout (hi/lo tf32), coalesced for phase 2.
// ---------------------------------------------------------------------------
__global__ void init_kernel(const float* __restrict__ h0, const float* __restrict__ c0,
                            const float* __restrict__ Wx, const float* __restrict__ Wh) {
    int idx = blockIdx.x * blockDim.x + threadIdx.x;
    if (idx < Bn * Nn * Hn) {
        d_hbuf[0][idx] = h0[idx];
        d_cbuf[idx]    = c0[idx];
    }
    if (idx < 9 * 32 * 32) {
        int kk    = idx >> 10;          // /1024
        int rem   = idx & 1023;
        int ntile = rem >> 5;
        int lane  = rem & 31;
        int g   = lane >> 2;
        int tig = lane & 3;
        int col = ntile * 8 + g;
        int kr0 = kk * 8 + tig;
        int kr1 = kr0 + 4;
        float w0 = (kr0 < Dn) ? Wx[kr0 * G4 + col] : Wh[(kr0 - Dn) * G4 + col];
        float w1 = (kr1 < Dn) ? Wx[kr1 * G4 + col] : Wh[(kr1 - Dn) * G4 + col];
        unsigned h0u, l0u, h1u, l1u;
        splitf(w0, h0u, l0u);
        splitf(w1, h1u, l1u);
        float* dst = d_Wfrag + (size_t)idx * 4;
        dst[0] = __uint_as_float(h0u);
        dst[1] = __uint_as_float(h1u);
        dst[2] = __uint_as_float(l0u);
        dst[3] = __uint_as_float(l1u);
    }
}

// phase-1 mma triplet (error-compensated tf32) into three distinct acc copies
#define P1_TRIPLE(ACC0, ACC1, ACC2, B0H, B1H, B0L, B1L)                        \
    mma_tf32(ACC0, a0h, a1h, a2h, a3h, B0H, B1H);                              \
    mma_tf32(ACC1, a0h, a1h, a2h, a3h, B0L, B1L);                              \
    mma_tf32(ACC2, a0l, a1l, a2l, a3l, B0H, B1H);

// ---------------------------------------------------------------------------
// One recurrent step, fused:
//   ah(16x72) = adj_t(16x512) @ [x_t | h](512x72)     (compensated tf32)
//   g (16x256) = ah @ [Wx;Wh](72x256)                 (compensated tf32)
//   LSTM gates -> h,c
// ---------------------------------------------------------------------------
__global__ void __launch_bounds__(TPB) step_kernel(
    const float* __restrict__ x,
    const float* __restrict__ adj,
    const float* __restrict__ b_gates,
    int t)
{
    extern __shared__ float smem[];
    float* smAhi = smem + SM_AHI;
    float* smAlo = smem + SM_ALO;
    float* ah    = smem + SM_AH;
    float* gsm   = smem + SM_AHI;   // overlays A frags (dead after phase 1)

    const int b    = blockIdx.y;
    const int n0   = blockIdx.x * ROWS;
    const int tid  = threadIdx.x;
    const int lane = tid & 31;
    const int w    = tid >> 5;      // warp 0..7
    const int g    = lane >> 2;     // mma group 0..7
    const int tig  = lane & 3;      // thread-in-group 0..3

    const float* h_in  = d_hbuf[t & 1] + (size_t)b * Nn * Hn;
    const float* Abase = adj + (((size_t)b * Sn + t) * Nn + n0) * Nn;
    const float* xs    = x + ((size_t)b * Sn + t) * Nn * Dn;

    // zero x-region of ah (rows 0..15, cols 0..7) for atomic reduction
    if (tid < 128) ah[(tid >> 3) * 76 + (tid & 7)] = 0.0f;

    // ---- Stage A tile (16 x 512) as hi/lo tf32 mma A-fragments ----
    #pragma unroll 4
    for (int idx = tid; idx < ROWS * Nn; idx += TPB) {
        int n = idx >> 9;
        int m = idx & 511;
        float v = Abase[(size_t)n * Nn + m];
        int kc = m >> 3;
        int c  = m & 7;
        int i  = (n >> 3) + 2 * (c >> 2);
        int ln = ((n & 7) << 2) | (c & 3);
        unsigned hi, lo;
        splitf(v, hi, lo);
        smAhi[((kc << 5) + ln) * 4 + i] = __uint_as_float(hi);
        smAlo[((kc << 5) + ln) * 4 + i] = __uint_as_float(lo);
    }
    __syncthreads();

    // ---- Phase 1: warp w owns h-feature tile (F cols 8+8w..15+8w) for all K,
    //      plus the x tile (F cols 0..7) for K-chunk range [8w, 8w+8) ----
    float acch[6][4], accx[6][4];
    #pragma unroll
    for (int q = 0; q < 6; ++q)
        #pragma unroll
        for (int i = 0; i < 4; ++i) { acch[q][i] = 0.0f; accx[q][i] = 0.0f; }

    const float* hj = h_in + 8 * w;   // this warp's h column base

    #pragma unroll 2
    for (int kc2 = 0; kc2 < 32; ++kc2) {
        // even kc -> copies 0..2, odd kc -> copies 3..5
        {
            const int kc = 2 * kc2;
            const float4 fh = *(const float4*)(smAhi + (kc * 32 + lane) * 4);
            const float4 fl = *(const float4*)(smAlo + (kc * 32 + lane) * 4);
            unsigned a0h = __float_as_uint(fh.x), a1h = __float_as_uint(fh.y);
            unsigned a2h = __float_as_uint(fh.z), a3h = __float_as_uint(fh.w);
            unsigned a0l = __float_as_uint(fl.x), a1l = __float_as_uint(fl.y);
            unsigned a2l = __float_as_uint(fl.z), a3l = __float_as_uint(fl.w);
            float b0v = hj[(kc * 8 + tig) * Hn + g];
            float b1v = hj[(kc * 8 + tig + 4) * Hn + g];
            unsigned b0h, b0l, b1h, b1l;
            splitf(b0v, b0h, b0l);
            splitf(b1v, b1h, b1l);
            P1_TRIPLE(acch[0], acch[1], acch[2], b0h, b1h, b0l, b1l)
            if ((kc >> 3) == w) {
                float x0 = xs[(kc * 8 + tig) * Dn + g];
                float x1 = xs[(kc * 8 + tig + 4) * Dn + g];
                unsigned x0h, x0l, x1h, x1l;
                splitf(x0, x0h, x0l);
                splitf(x1, x1h, x1l);
                mma_tf32(accx[0], a0h, a1h, a2h, a3h, x0h, x1h);
                mma_tf32(accx[1], a0h, a1h, a2h, a3h, x0l, x1l);
                mma_tf32(accx[2], a0l, a1l, a2l, a3l, x0h, x1h);
            }
        }
        {
            const int kc = 2 * kc2 + 1;
            const float4 fh = *(const float4*)(smAhi + (kc * 32 + lane) * 4);
            const float4 fl = *(const float4*)(smAlo + (kc * 32 + lane) * 4);
            unsigned a0h = __float_as_uint(fh.x), a1h = __float_as_uint(fh.y);
            unsigned a2h = __float_as_uint(fh.z), a3h = __float_as_uint(fh.w);
            unsigned a0l = __float_as_uint(fl.x), a1l = __float_as_uint(fl.y);
            unsigned a2l = __float_as_uint(fl.z), a3l = __float_as_uint(fl.w);
            float b0v = hj[(kc * 8 + tig) * Hn + g];
            float b1v = hj[(kc * 8 + tig + 4) * Hn + g];
            unsigned b0h, b0l, b1h, b1l;
            splitf(b0v, b0h, b0l);
            splitf(b1v, b1h, b1l);
            P1_TRIPLE(acch[3], acch[4], acch[5], b0h, b1h, b0l, b1l)
            if ((kc >> 3) == w) {
                float x0 = xs[(kc * 8 + tig) * Dn + g];
                float x1 = xs[(kc * 8 + tig + 4) * Dn + g];
                unsigned x0h, x0l, x1h, x1l;
                splitf(x0, x0h, x0l);
                splitf(x1, x1h, x1l);
                mma_tf32(accx[3], a0h, a1h, a2h, a3h, x0h, x1h);
                mma_tf32(accx[4], a0h, a1h, a2h, a3h, x0l, x1l);
                mma_tf32(accx[5], a0l, a1l, a2l, a3l, x0h, x1h);
            }
        }
    }

    // collapse copies and store ah
    {
        float sh[4], sx[4];
        #pragma unroll
        for (int i = 0; i < 4; ++i) {
            sh[i] = ((acch[0][i] + acch[1][i]) + (acch[2][i] + acch[3][i])) + (acch[4][i] + acch[5][i]);
            sx[i] = ((accx[0][i] + accx[1][i]) + (accx[2][i] + accx[3][i])) + (accx[4][i] + accx[5][i]);
        }
        const int cb = 8 * (w + 1);
        ah[g * 76 + cb + 2 * tig]           = sh[0];
        ah[g * 76 + cb + 2 * tig + 1]       = sh[1];
        ah[(g + 8) * 76 + cb + 2 * tig]     = sh[2];
        ah[(g + 8) * 76 + cb + 2 * tig + 1] = sh[3];
        atomicAdd(&ah[g * 76 + 2 * tig],           sx[0]);
        atomicAdd(&ah[g * 76 + 2 * tig + 1],       sx[1]);
        atomicAdd(&ah[(g + 8) * 76 + 2 * tig],     sx[2]);
        atomicAdd(&ah[(g + 8) * 76 + 2 * tig + 1], sx[3]);
    }
    __syncthreads();

    // ---- Phase 2: g(16x256) = ah(16x72) @ W(72x256); warp w owns cols [32w,32w+32) ----
    float acc2[4][4];
    #pragma unroll
    for (int nt = 0; nt < 4; ++nt)
        #pragma unroll
        for (int i = 0; i < 4; ++i) acc2[nt][i] = 0.0f;

    #pragma unroll
    for (int kk = 0; kk < 9; ++kk) {
        float v0 = ah[g * 76 + kk * 8 + tig];
        float v1 = ah[(g + 8) * 76 + kk * 8 + tig];
        float v2 = ah[g * 76 + kk * 8 + tig + 4];
        float v3 = ah[(g + 8) * 76 + kk * 8 + tig + 4];
        unsigned A0h, A0l, A1h, A1l, A2h, A2l, A3h, A3l;
        splitf(v0, A0h, A0l);
        splitf(v1, A1h, A1l);
        splitf(v2, A2h, A2l);
        splitf(v3, A3h, A3l);
        float4 q[4];
        #pragma unroll
        for (int nt = 0; nt < 4; ++nt)
            q[nt] = *(const float4*)(d_Wfrag + ((size_t)(kk * 32 + (w << 2) + nt) * 32 + lane) * 4);
        #pragma unroll
        for (int nt = 0; nt < 4; ++nt)
            mma_tf32(acc2[nt], A0h, A1h, A2h, A3h, __float_as_uint(q[nt].x), __float_as_uint(q[nt].y));
        #pragma unroll
        for (int nt = 0; nt < 4; ++nt)
            mma_tf32(acc2[nt], A0h, A1h, A2h, A3h, __float_as_uint(q[nt].z), __float_as_uint(q[nt].w));
        #pragma unroll
        for (int nt = 0; nt < 4; ++nt)
            mma_tf32(acc2[nt], A0l, A1l, A2l, A3l, __float_as_uint(q[nt].x), __float_as_uint(q[nt].y));
    }

    // store gate pre-activations (gsm overlays A-frag smem; all reads done)
    #pragma unroll
    for (int nt = 0; nt < 4; ++nt) {
        int col = w * 32 + nt * 8 + 2 * tig;
        gsm[g * 260 + col]           = acc2[nt][0];
        gsm[g * 260 + col + 1]       = acc2[nt][1];
        gsm[(g + 8) * 260 + col]     = acc2[nt][2];
        gsm[(g + 8) * 260 + col + 1] = acc2[nt][3];
    }
    __syncthreads();

    // ---- LSTM gates ----
    float* h_o = d_hbuf[(t + 1) & 1] + ((size_t)b * Nn + n0) * Hn;
    float* c_p = d_cbuf + ((size_t)b * Nn + n0) * Hn;
    #pragma unroll
    for (int e = tid; e < ROWS * Hn; e += TPB) {
        int r = e >> 6;
        int j = e & 63;
        float gi = gsm[r * 260 + j]       + b_gates[j];
        float gf = gsm[r * 260 + 64 + j]  + b_gates[64 + j];
        float go = gsm[r * 260 + 128 + j] + b_gates[128 + j];
        float gg = gsm[r * 260 + 192 + j] + b_gates[192 + j];
        float i_ = sigmoidf_fast(gi);
        float f_ = sigmoidf_fast(gf);
        float o_ = sigmoidf_fast(go);
        float G  = tanhf_fast(gg);
        float cn = f_ * c_p[r * 64 + j] + i_ * G;
        c_p[r * 64 + j] = cn;
        h_o[r * 64 + j] = o_ * tanhf_fast(cn);
    }
}

// ---------------------------------------------------------------------------
// Readout: out = relu(h[:,0,:] @ W1 + b1) @ W2 + b2
// ---------------------------------------------------------------------------
__global__ void readout_kernel(const float* __restrict__ W1, const float* __restrict__ b1,
                               const float* __restrict__ W2, const float* __restrict__ b2,
                               float* __restrict__ out)
{
    __shared__ float hid[Bn][Hn / 2];
    int tid = threadIdx.x;
    const float* h = d_hbuf[0];   // Sn=96 even -> final state in buffer 0
    if (tid < Bn * (Hn / 2)) {
        int b = tid / (Hn / 2);
        int u = tid % (Hn / 2);
        float s = b1[u];
        #pragma unroll 8
        for (int k = 0; k < Hn; ++k)
            s += h[((size_t)b * Nn + 0) * Hn + k] * W1[k * (Hn / 2) + u];
        hid[b][u] = fmaxf(s, 0.0f);
    }
    __syncthreads();
    if (tid < Bn * OUTn) {
        int b = tid / OUTn;
        int o = tid % OUTn;
        float s = b2[o];
        #pragma unroll
        for (int u = 0; u < Hn / 2; ++u)
            s += hid[b][u] * W2[u * OUTn + o];
        out[b * OUTn + o] = s;
    }
}

extern "C" void kernel_launch(void* const* d_in, const int* in_sizes, int n_in,
                              void* d_out, int out_size)
{
    const float* x   = (const float*)d_in[0];
    const float* adj = (const float*)d_in[1];
    const float* h0  = (const float*)d_in[2];
    const float* c0  = (const float*)d_in[3];
    const float* Wx  = (const float*)d_in[4];
    const float* Wh  = (const float*)d_in[5];
    const float* bg  = (const float*)d_in[6];
    const float* W1  = (const float*)d_in[7];
    const float* b1  = (const float*)d_in[8];
    const float* W2  = (const float*)d_in[9];
    const float* b2  = (const float*)d_in[10];
    float* out = (float*)d_out;

    cudaFuncSetAttribute(step_kernel, cudaFuncAttributeMaxDynamicSharedMemorySize, SMEM_BYTES);

    init_kernel<<<(Bn * Nn * Hn + 255) / 256, 256>>>(h0, c0, Wx, Wh);

    dim3 grid(Nn / ROWS, Bn);   // 32 x 4 = 128 CTAs
    for (int t = 0; t < Sn; ++t) {
        step_kernel<<<grid, TPB, SMEM_BYTES>>>(x, adj, bg, t);
    }

    readout_kernel<<<1, 128>>>(W1, b1, W2, b2, out);
}

// round 4
// speedup vs baseline: 1.3088x; 1.3088x over previous
#include <cuda_runtime.h>
#include <cuda_bf16.h>
#include <cstdint>

// Problem constants
#define Bn   4
#define Sn   96
#define Nn   512
#define Dn   8
#define Hn   64
#define G4   256
#define OUTn 24

#define ROWS 16
#define TPB  256
#define NTIL 32              // Nn/ROWS
#define GRID_CTAS 128        // NTIL * Bn  (<=148 SMs -> all co-resident)

// Dynamic smem layout (floats)
#define SM_AHI 0             // 8192  : A-frag hi [(kc*32+lane)*4 + i]   (gsm overlays)
#define SM_ALO 8192          // 8192  : A-frag lo
#define SM_AH  16384         // 1216  : ah (16 x 76)
#define SM_C   17600         // 1024  : cell state (persistent across steps)
#define SM_HS  18624         // 1024  : h_new scratch
#define SMEM_FLOATS 19648
#define SMEM_BYTES  (SMEM_FLOATS * 4)

// ---------------- persistent device state ----------------
// h fragments, double buffered: [par][b][kc(64)][j(8)][lane(32)] of {b0h,b1h,b0l,b1l}
__device__ float4 d_Ffrag[2 * Bn * 64 * 8 * 32];
// x fragments prepacked for all steps: [t][b][kc(64)][lane(32)]
__device__ float4 d_Xfrag[Sn * Bn * 64 * 32];
// W fragments: [kk(9)][ntile(32)][lane(32)]
__device__ float4 d_Wfrag4[9 * 32 * 32];
__device__ float  d_hfinal[Bn * Hn];
__device__ unsigned d_barcnt;
__device__ unsigned d_barflag;

// ---------------- helpers ----------------
__device__ __forceinline__ void tsplit(float v, float& hi, float& lo) {
    hi = __uint_as_float(__float_as_uint(v) & 0xFFFFE000u);
    lo = v - hi;
}

__device__ __forceinline__ void mma_tf32(float c[4],
                                         float a0, float a1, float a2, float a3,
                                         float b0, float b1) {
    asm volatile(
        "mma.sync.aligned.m16n8k8.row.col.f32.tf32.tf32.f32 "
        "{%0,%1,%2,%3}, {%4,%5,%6,%7}, {%8,%9}, {%0,%1,%2,%3};\n"
        : "+f"(c[0]), "+f"(c[1]), "+f"(c[2]), "+f"(c[3])
        : "r"(__float_as_uint(a0)), "r"(__float_as_uint(a1)),
          "r"(__float_as_uint(a2)), "r"(__float_as_uint(a3)),
          "r"(__float_as_uint(b0)), "r"(__float_as_uint(b1)));
}

__device__ __forceinline__ float sigmoidf_fast(float x) { return 1.0f / (1.0f + __expf(-x)); }
__device__ __forceinline__ float tanhf_fast(float x)    { return 1.0f - 2.0f / (__expf(2.0f * x) + 1.0f); }

__device__ __forceinline__ void grid_barrier(unsigned epoch) {
    __syncthreads();
    if (threadIdx.x == 0) {
        __threadfence();
        unsigned old = atomicAdd(&d_barcnt, 1u);
        if (old == epoch * GRID_CTAS - 1u) {
            asm volatile("st.release.gpu.u32 [%0], %1;" :: "l"(&d_barflag), "r"(epoch) : "memory");
        } else {
            unsigned v;
            do {
                __nanosleep(64);
                asm volatile("ld.acquire.gpu.u32 %0, [%1];" : "=r"(v) : "l"(&d_barflag) : "memory");
            } while (v < epoch);
        }
    }
    __syncthreads();
}

// ---------------- init: reset barrier, pack W / x / h0 fragments ----------------
__global__ void init_kernel(const float* __restrict__ x,
                            const float* __restrict__ h0,
                            const float* __restrict__ Wx,
                            const float* __restrict__ Wh) {
    int idx = blockIdx.x * blockDim.x + threadIdx.x;
    if (idx == 0) { d_barcnt = 0; d_barflag = 0; }

    // W fragments (9216 entries)
    if (idx < 9 * 32 * 32) {
        int kk    = idx >> 10;
        int rem   = idx & 1023;
        int ntile = rem >> 5;
        int lane  = rem & 31;
        int g = lane >> 2, tig = lane & 3;
        int col = ntile * 8 + g;
        int kr0 = kk * 8 + tig;
        int kr1 = kr0 + 4;
        float w0 = (kr0 < Dn) ? Wx[kr0 * G4 + col] : Wh[(kr0 - Dn) * G4 + col];
        float w1 = (kr1 < Dn) ? Wx[kr1 * G4 + col] : Wh[(kr1 - Dn) * G4 + col];
        float h0f, l0f, h1f, l1f;
        tsplit(w0, h0f, l0f);
        tsplit(w1, h1f, l1f);
        d_Wfrag4[idx] = make_float4(h0f, h1f, l0f, l1f);
    }

    // h0 fragments into parity 0 (65536 entries)
    if (idx < Bn * 64 * 8 * 32) {
        int lane = idx & 31;
        int j    = (idx >> 5) & 7;
        int kc   = (idx >> 8) & 63;
        int b    = idx >> 14;
        int g = lane >> 2, tig = lane & 3;
        float b0 = h0[((size_t)b * Nn + kc * 8 + tig) * Hn + j * 8 + g];
        float b1 = h0[((size_t)b * Nn + kc * 8 + tig + 4) * Hn + j * 8 + g];
        float bh0, bl0, bh1, bl1;
        tsplit(b0, bh0, bl0);
        tsplit(b1, bh1, bl1);
        d_Ffrag[(((size_t)b * 64 + kc) * 8 + j) * 32 + lane] = make_float4(bh0, bh1, bl0, bl1);
    }

    // x fragments for all steps (786432 entries)
    if (idx < Sn * Bn * 64 * 32) {
        int lane = idx & 31;
        int kc   = (idx >> 5) & 63;
        int b    = (idx >> 11) & 3;
        int t    = idx >> 13;
        int g = lane >> 2, tig = lane & 3;
        const float* xs = x + ((size_t)b * Sn + t) * Nn * Dn;
        float x0 = xs[(kc * 8 + tig) * Dn + g];
        float x1 = xs[(kc * 8 + tig + 4) * Dn + g];
        float xh0, xl0, xh1, xl1;
        tsplit(x0, xh0, xl0);
        tsplit(x1, xh1, xl1);
        d_Xfrag[(((size_t)t * Bn + b) * 64 + kc) * 32 + lane] = make_float4(xh0, xh1, xl0, xl1);
    }
}

// ---------------- A tile staging ----------------
// Coalesced LDG.128 of adj rows; scalar STS into mma-frag-contiguous layout
// smA[(kc*32 + ln)*4 + i] so phase 1 reads one LDS.128 per kc per array.
__device__ __forceinline__ void stageA(const float* __restrict__ Abase, float* __restrict__ smA) {
    #pragma unroll
    for (int r = 0; r < 8; ++r) {
        int idx = threadIdx.x + r * TPB;      // 0..2047 float4s
        int n  = idx >> 7;                    // node row 0..15
        int mq = idx & 127;                   // float4 index within row
        int kc = mq >> 1;                     // 8-col chunk
        int c4 = mq & 1;                      // half of chunk
        int i  = (n >> 3) + 2 * c4;           // a-reg index
        int lnb = (n & 7) << 2;               // lane base
        float4 v = *(const float4*)(Abase + (size_t)n * Nn + (size_t)mq * 4);
        float hx, lx;
        tsplit(v.x, hx, lx);
        smA[SM_AHI + ((kc << 5) + (lnb | 0)) * 4 + i] = hx;
        smA[SM_ALO + ((kc << 5) + (lnb | 0)) * 4 + i] = lx;
        tsplit(v.y, hx, lx);
        smA[SM_AHI + ((kc << 5) + (lnb | 1)) * 4 + i] = hx;
        smA[SM_ALO + ((kc << 5) + (lnb | 1)) * 4 + i] = lx;
        tsplit(v.z, hx, lx);
        smA[SM_AHI + ((kc << 5) + (lnb | 2)) * 4 + i] = hx;
        smA[SM_ALO + ((kc << 5) + (lnb | 2)) * 4 + i] = lx;
        tsplit(v.w, hx, lx);
        smA[SM_AHI + ((kc << 5) + (lnb | 3)) * 4 + i] = hx;
        smA[SM_ALO + ((kc << 5) + (lnb | 3)) * 4 + i] = lx;
    }
}

// ---------------- the persistent kernel ----------------
__global__ void __launch_bounds__(TPB, 1) persistent_kernel(
    const float* __restrict__ adj,
    const float* __restrict__ c0,
    const float* __restrict__ b_gates,
    const float* __restrict__ W1, const float* __restrict__ b1,
    const float* __restrict__ W2, const float* __restrict__ b2,
    float* __restrict__ out)
{
    extern __shared__ float smem[];
    float* ah  = smem + SM_AH;
    float* c_s = smem + SM_C;
    float* hs  = smem + SM_HS;
    float* gsm = smem + SM_AHI;   // overlays A frags (dead after phase 1)

    const int b    = blockIdx.y;
    const int n0   = blockIdx.x * ROWS;
    const int tid  = threadIdx.x;
    const int lane = tid & 31;
    const int w    = tid >> 5;
    const int g    = lane >> 2;
    const int tig  = lane & 3;
    const int kc0  = n0 >> 3;

    // load persistent cell state
    #pragma unroll
    for (int e = tid; e < ROWS * Hn; e += TPB)
        c_s[e] = c0[((size_t)b * Nn + n0) * Hn + e];

    // stage A for t = 0
    stageA(adj + (((size_t)b * Sn + 0) * Nn + n0) * Nn, smem);

    for (int t = 0; t < Sn; ++t) {
        const int par = t & 1;

        // zero x-region of ah for atomic reduction
        if (tid < 128) ah[(tid >> 3) * 76 + (tid & 7)] = 0.0f;
        __syncthreads();   // A tile + zero visible

        // ================= Phase 1 =================
        float acch[6][4];
        #pragma unroll
        for (int q2 = 0; q2 < 6; ++q2)
            #pragma unroll
            for (int i = 0; i < 4; ++i) acch[q2][i] = 0.0f;

        const float4* fb = d_Ffrag + (size_t)(par * Bn + b) * (64 * 8 * 32) + w * 32 + lane;
        float4 q[4], qn[4];
        #pragma unroll
        for (int u = 0; u < 4; ++u) q[u] = fb[(size_t)u * 256];

        for (int kcb = 0; kcb < 64; kcb += 4) {
            const bool pf = (kcb + 4) < 64;
            #pragma unroll
            for (int u = 0; u < 4; ++u)
                if (pf) qn[u] = fb[(size_t)(kcb + 4 + u) * 256];
            #pragma unroll
            for (int u = 0; u < 4; ++u) {
                const int kc = kcb + u;
                const float4 fh = *(const float4*)(smem + SM_AHI + ((kc << 5) + lane) * 4);
                const float4 fl = *(const float4*)(smem + SM_ALO + ((kc << 5) + lane) * 4);
                const int p = (u & 1) * 3;
                mma_tf32(acch[p + 0], fh.x, fh.y, fh.z, fh.w, q[u].x, q[u].y);
                mma_tf32(acch[p + 1], fh.x, fh.y, fh.z, fh.w, q[u].z, q[u].w);
                mma_tf32(acch[p + 2], fl.x, fl.y, fl.z, fl.w, q[u].x, q[u].y);
            }
            #pragma unroll
            for (int u = 0; u < 4; ++u) q[u] = qn[u];
        }

        // x pass: warp w covers kc in [8w, 8w+8)
        float accx[3][4];
        #pragma unroll
        for (int p = 0; p < 3; ++p)
            #pragma unroll
            for (int i = 0; i < 4; ++i) accx[p][i] = 0.0f;
        {
            const float4* xb = d_Xfrag + (size_t)(t * Bn + b) * (64 * 32) + lane;
            #pragma unroll
            for (int kcl = 0; kcl < 8; ++kcl) {
                const int kc = 8 * w + kcl;
                float4 xq = xb[(size_t)kc * 32];
                const float4 fh = *(const float4*)(smem + SM_AHI + ((kc << 5) + lane) * 4);
                const float4 fl = *(const float4*)(smem + SM_ALO + ((kc << 5) + lane) * 4);
                mma_tf32(accx[0], fh.x, fh.y, fh.z, fh.w, xq.x, xq.y);
                mma_tf32(accx[1], fh.x, fh.y, fh.z, fh.w, xq.z, xq.w);
                mma_tf32(accx[2], fl.x, fl.y, fl.z, fl.w, xq.x, xq.y);
            }
        }

        // collapse + store ah
        {
            float sh[4], sx[4];
            #pragma unroll
            for (int i = 0; i < 4; ++i) {
                sh[i] = ((acch[0][i] + acch[1][i]) + (acch[2][i] + acch[3][i])) + (acch[4][i] + acch[5][i]);
                sx[i] = (accx[0][i] + accx[1][i]) + accx[2][i];
            }
            const int cb = 8 * (w + 1);
            ah[g * 76 + cb + 2 * tig]           = sh[0];
            ah[g * 76 + cb + 2 * tig + 1]       = sh[1];
            ah[(g + 8) * 76 + cb + 2 * tig]     = sh[2];
            ah[(g + 8) * 76 + cb + 2 * tig + 1] = sh[3];
            atomicAdd(&ah[g * 76 + 2 * tig],           sx[0]);
            atomicAdd(&ah[g * 76 + 2 * tig + 1],       sx[1]);
            atomicAdd(&ah[(g + 8) * 76 + 2 * tig],     sx[2]);
            atomicAdd(&ah[(g + 8) * 76 + 2 * tig + 1], sx[3]);
        }
        __syncthreads();

        // ================= Phase 2 =================
        float acc2[2][4][4];
        #pragma unroll
        for (int h2 = 0; h2 < 2; ++h2)
            #pragma unroll
            for (int nt = 0; nt < 4; ++nt)
                #pragma unroll
                for (int i = 0; i < 4; ++i) acc2[h2][nt][i] = 0.0f;

        #pragma unroll
        for (int kk = 0; kk < 9; ++kk) {
            float v0 = ah[g * 76 + kk * 8 + tig];
            float v1 = ah[(g + 8) * 76 + kk * 8 + tig];
            float v2 = ah[g * 76 + kk * 8 + tig + 4];
            float v3 = ah[(g + 8) * 76 + kk * 8 + tig + 4];
            float A0h, A0l, A1h, A1l, A2h, A2l, A3h, A3l;
            tsplit(v0, A0h, A0l);
            tsplit(v1, A1h, A1l);
            tsplit(v2, A2h, A2l);
            tsplit(v3, A3h, A3l);
            const int hsel = kk & 1;
            #pragma unroll
            for (int nt = 0; nt < 4; ++nt) {
                float4 qw = d_Wfrag4[(size_t)(kk * 32 + (w << 2) + nt) * 32 + lane];
                mma_tf32(acc2[hsel][nt], A0h, A1h, A2h, A3h, qw.x, qw.y);
                mma_tf32(acc2[hsel][nt], A0h, A1h, A2h, A3h, qw.z, qw.w);
                mma_tf32(acc2[hsel][nt], A0l, A1l, A2l, A3l, qw.x, qw.y);
            }
        }

        #pragma unroll
        for (int nt = 0; nt < 4; ++nt) {
            int col = w * 32 + nt * 8 + 2 * tig;
            gsm[g * 260 + col]           = acc2[0][nt][0] + acc2[1][nt][0];
            gsm[g * 260 + col + 1]       = acc2[0][nt][1] + acc2[1][nt][1];
            gsm[(g + 8) * 260 + col]     = acc2[0][nt][2] + acc2[1][nt][2];
            gsm[(g + 8) * 260 + col + 1] = acc2[0][nt][3] + acc2[1][nt][3];
        }
        __syncthreads();

        // ================= Gates =================
        #pragma unroll
        for (int e = tid; e < ROWS * Hn; e += TPB) {
            int r = e >> 6;
            int j = e & 63;
            float gi = gsm[r * 260 + j]       + b_gates[j];
            float gf = gsm[r * 260 + 64 + j]  + b_gates[64 + j];
            float go = gsm[r * 260 + 128 + j] + b_gates[128 + j];
            float gg = gsm[r * 260 + 192 + j] + b_gates[192 + j];
            float i_ = sigmoidf_fast(gi);
            float f_ = sigmoidf_fast(gf);
            float o_ = sigmoidf_fast(go);
            float G  = tanhf_fast(gg);
            float cn = f_ * c_s[e] + i_ * G;
            c_s[e] = cn;
            hs[e]  = o_ * tanhf_fast(cn);
        }
        __syncthreads();

        // ---- write h fragments for next step ----
        {
            const int npar = par ^ 1;
            float4* dst = d_Ffrag + (size_t)(npar * Bn + b) * (64 * 8 * 32);
            #pragma unroll
            for (int r2 = 0; r2 < 2; ++r2) {
                int e   = tid + TPB * r2;     // 0..511
                int kcl = e >> 8;
                int rem = e & 255;
                int j   = rem >> 5;
                int ln  = rem & 31;
                int g2 = ln >> 2, tg = ln & 3;
                float b0v = hs[(kcl * 8 + tg) * 64 + j * 8 + g2];
                float b1v = hs[(kcl * 8 + tg + 4) * 64 + j * 8 + g2];
                float bh0, bl0, bh1, bl1;
                tsplit(b0v, bh0, bl0);
                tsplit(b1v, bh1, bl1);
                dst[(size_t)(kc0 + kcl) * 256 + j * 32 + ln] = make_float4(bh0, bh1, bl0, bl1);
            }
        }
        if (t == Sn - 1 && blockIdx.x == 0 && tid < Hn)
            d_hfinal[b * Hn + tid] = hs[tid];

        // ---- prefetch next A tile into smem before the barrier ----
        if (t < Sn - 1)
            stageA(adj + (((size_t)b * Sn + (t + 1)) * Nn + n0) * Nn, smem);

        grid_barrier((unsigned)(t + 1));
    }

    // ================= Readout (CTA 0 only) =================
    if (blockIdx.x == 0 && blockIdx.y == 0) {
        float* hid = smem + SM_AH;   // reuse smem: Bn x 32
        if (tid < Bn * (Hn / 2)) {
            int bb = tid / (Hn / 2);
            int u  = tid % (Hn / 2);
            float s = b1[u];
            #pragma unroll 8
            for (int k = 0; k < Hn; ++k)
                s += d_hfinal[bb * Hn + k] * W1[k * (Hn / 2) + u];
            hid[bb * (Hn / 2) + u] = fmaxf(s, 0.0f);
        }
        __syncthreads();
        if (tid < Bn * OUTn) {
            int bb = tid / OUTn;
            int o  = tid % OUTn;
            float s = b2[o];
            #pragma unroll
            for (int u = 0; u < Hn / 2; ++u)
                s += hid[bb * (Hn / 2) + u] * W2[u * OUTn + o];
            out[bb * OUTn + o] = s;
        }
    }
}

extern "C" void kernel_launch(void* const* d_in, const int* in_sizes, int n_in,
                              void* d_out, int out_size)
{
    const float* x   = (const float*)d_in[0];
    const float* adj = (const float*)d_in[1];
    const float* h0  = (const float*)d_in[2];
    const float* c0  = (const float*)d_in[3];
    const float* Wx  = (const float*)d_in[4];
    const float* Wh  = (const float*)d_in[5];
    const float* bg  = (const float*)d_in[6];
    const float* W1  = (const float*)d_in[7];
    const float* b1  = (const float*)d_in[8];
    const float* W2  = (const float*)d_in[9];
    const float* b2  = (const float*)d_in[10];
    float* out = (float*)d_out;

    cudaFuncSetAttribute(persistent_kernel,
                         cudaFuncAttributeMaxDynamicSharedMemorySize, SMEM_BYTES);

    init_kernel<<<(Sn * Bn * 64 * 32 + 255) / 256, 256>>>(x, h0, Wx, Wh);

    dim3 grid(NTIL, Bn);   // 32 x 4 = 128 CTAs, all resident
    persistent_kernel<<<grid, TPB, SMEM_BYTES>>>(adj, c0, bg, W1, b1, W2, b2, out);
}

// round 5
// speedup vs baseline: 2.6676x; 2.0382x over previous
#include <cuda_runtime.h>
#include <cuda_bf16.h>
#include <cstdint>

// Problem constants
#define Bn   4
#define Sn   96
#define Nn   512
#define Dn   8
#define Hn   64
#define OUTn 24

#define ROWS 16
#define TPB  256
#define NTIL 32              // Nn/ROWS
#define GRID_CTAS 128
#define KC   32              // K chunks of 16 (Nn/16)

// smem layout (float units)
#define SM_AHI 0             // 4224 u32 : A-frag hi [(kc*33+lane)*4 + i]
#define SM_ALO 4224          // 4224 u32 : A-frag lo
#define SM_W   8448          // 20480    : W fragments (5120 uint4)
#define SM_AH  28928         // 1280     : ah (16 x 80, cols 72..79 zero pad)
#define SM_HS  30208         // 1024     : h_new scratch
#define SMEM_FLOATS 31232
#define SMEM_BYTES  (SMEM_FLOATS * 4)

// ---------------- persistent device state ----------------
// h fragments (bf16 hi/lo packed), double buffered: [par][b][kc(32)][j(8)][lane(32)]
__device__ uint4 d_Ffrag[2 * Bn * KC * 8 * 32];
// x fragments for all steps: [t][b][kc(32)][lane(32)]
__device__ uint4 d_Xfrag[Sn * Bn * KC * 32];
// W fragments: [kk(5)][ntile(32)][lane(32)]
__device__ uint4 d_Wfrag4[5 * 32 * 32];
__device__ float  d_hfinal[Bn * Hn];
__device__ unsigned d_barcnt;
__device__ unsigned d_barflag;

// ---------------- helpers ----------------
// round-to-nearest bf16 split of a float pair; packed bf16x2 (low = first elem)
__device__ __forceinline__ void bsplit2(float x, float y, unsigned& h, unsigned& l) {
    __nv_bfloat162 hb = __float22bfloat162_rn(make_float2(x, y));
    float2 hf = __bfloat1622float2(hb);
    __nv_bfloat162 lb = __float22bfloat162_rn(make_float2(x - hf.x, y - hf.y));
    h = *reinterpret_cast<unsigned*>(&hb);
    l = *reinterpret_cast<unsigned*>(&lb);
}

__device__ __forceinline__ void mma_bf16(float c[4],
                                         unsigned a0, unsigned a1, unsigned a2, unsigned a3,
                                         unsigned b0, unsigned b1) {
    asm volatile(
        "mma.sync.aligned.m16n8k16.row.col.f32.bf16.bf16.f32 "
        "{%0,%1,%2,%3}, {%4,%5,%6,%7}, {%8,%9}, {%0,%1,%2,%3};\n"
        : "+f"(c[0]), "+f"(c[1]), "+f"(c[2]), "+f"(c[3])
        : "r"(a0), "r"(a1), "r"(a2), "r"(a3), "r"(b0), "r"(b1));
}

__device__ __forceinline__ float sigmoidf_fast(float x) { return 1.0f / (1.0f + __expf(-x)); }
__device__ __forceinline__ float tanhf_fast(float x)    { return 1.0f - 2.0f / (__expf(2.0f * x) + 1.0f); }

__device__ __forceinline__ void grid_barrier(unsigned epoch) {
    __syncthreads();
    if (threadIdx.x == 0) {
        __threadfence();
        unsigned old = atomicAdd(&d_barcnt, 1u);
        if (old == epoch * GRID_CTAS - 1u) {
            asm volatile("st.release.gpu.u32 [%0], %1;" :: "l"(&d_barflag), "r"(epoch) : "memory");
        } else {
            unsigned v;
            do {
                __nanosleep(32);
                asm volatile("ld.acquire.gpu.u32 %0, [%1];" : "=r"(v) : "l"(&d_barflag) : "memory");
            } while (v < epoch);
        }
    }
    __syncthreads();
}

// ---------------- init: reset barrier, pack W / x / h0 fragments (bf16) ----------------
__global__ void init_kernel(const float* __restrict__ x,
                            const float* __restrict__ h0,
                            const float* __restrict__ Wx,
                            const float* __restrict__ Wh) {
    int idx = blockIdx.x * blockDim.x + threadIdx.x;
    if (idx == 0) { d_barcnt = 0; d_barflag = 0; }

    // W fragments: 5120 entries. K rows 0..7 = Wx, 8..71 = Wh, 72..79 = 0 pad.
    if (idx < 5 * 32 * 32) {
        int kk    = idx >> 10;
        int rem   = idx & 1023;
        int ntile = rem >> 5;
        int lane  = rem & 31;
        int g = lane >> 2, tig = lane & 3;
        int col = ntile * 8 + g;
        auto wval = [&](int kr) -> float {
            if (kr >= 72) return 0.0f;
            return (kr < Dn) ? Wx[kr * 256 + col] : Wh[(kr - Dn) * 256 + col];
        };
        int k0 = kk * 16 + 2 * tig;
        unsigned b0h, b0l, b1h, b1l;
        bsplit2(wval(k0),     wval(k0 + 1), b0h, b0l);
        bsplit2(wval(k0 + 8), wval(k0 + 9), b1h, b1l);
        d_Wfrag4[idx] = make_uint4(b0h, b1h, b0l, b1l);
    }

    // h0 fragments into parity 0: 32768 entries
    if (idx < Bn * KC * 8 * 32) {
        int lane = idx & 31;
        int j    = (idx >> 5) & 7;
        int kc   = (idx >> 8) & 31;
        int b    = idx >> 13;
        int g = lane >> 2, tg = lane & 3;
        int col = j * 8 + g;
        const float* hb = h0 + (size_t)b * Nn * Hn;
        float v0 = hb[(kc * 16 + 2 * tg) * Hn + col];
        float v1 = hb[(kc * 16 + 2 * tg + 1) * Hn + col];
        float v2 = hb[(kc * 16 + 2 * tg + 8) * Hn + col];
        float v3 = hb[(kc * 16 + 2 * tg + 9) * Hn + col];
        unsigned b0h, b0l, b1h, b1l;
        bsplit2(v0, v1, b0h, b0l);
        bsplit2(v2, v3, b1h, b1l);
        d_Ffrag[((size_t)b * KC + kc) * 256 + j * 32 + lane] = make_uint4(b0h, b1h, b0l, b1l);
    }

    // x fragments: 393216 entries
    if (idx < Sn * Bn * KC * 32) {
        int lane = idx & 31;
        int kc   = (idx >> 5) & 31;
        int b    = (idx >> 10) & 3;
        int t    = idx >> 12;
        int g = lane >> 2, tg = lane & 3;
        const float* xs = x + ((size_t)b * Sn + t) * Nn * Dn;
        float v0 = xs[(kc * 16 + 2 * tg) * Dn + g];
        float v1 = xs[(kc * 16 + 2 * tg + 1) * Dn + g];
        float v2 = xs[(kc * 16 + 2 * tg + 8) * Dn + g];
        float v3 = xs[(kc * 16 + 2 * tg + 9) * Dn + g];
        unsigned b0h, b0l, b1h, b1l;
        bsplit2(v0, v1, b0h, b0l);
        bsplit2(v2, v3, b1h, b1l);
        d_Xfrag[(((size_t)t * Bn + b) * KC + kc) * 32 + lane] = make_uint4(b0h, b1h, b0l, b1l);
    }
}

// ---------------- stageA: load next adj tile / store bf16 fragments ----------------
__device__ __forceinline__ void stageA_load(const float* __restrict__ Abase, float4 av[8]) {
    #pragma unroll
    for (int r = 0; r < 8; ++r) {
        int idx = threadIdx.x + r * TPB;      // 0..2047 float4s
        int n  = idx >> 7;
        int mq = idx & 127;
        av[r] = *(const float4*)(Abase + (size_t)n * Nn + (size_t)mq * 4);
    }
}
__device__ __forceinline__ void stageA_store(const float4 av[8], unsigned* __restrict__ usm) {
    #pragma unroll
    for (int r = 0; r < 8; ++r) {
        int idx = threadIdx.x + r * TPB;
        int n  = idx >> 7;
        int mq = idx & 127;
        int kc = mq >> 2;
        int k  = (mq & 3) * 4;                 // 0,4,8,12
        int i  = ((n >> 3) & 1) + 2 * ((k >> 3) & 1);
        int l  = ((n & 7) << 2) | ((k >> 1) & 3);
        unsigned h0u, l0u, h1u, l1u;
        bsplit2(av[r].x, av[r].y, h0u, l0u);
        bsplit2(av[r].z, av[r].w, h1u, l1u);
        usm[SM_AHI + (kc * 33 + l)     * 4 + i] = h0u;
        usm[SM_AHI + (kc * 33 + l + 1) * 4 + i] = h1u;
        usm[SM_ALO + (kc * 33 + l)     * 4 + i] = l0u;
        usm[SM_ALO + (kc * 33 + l + 1) * 4 + i] = l1u;
    }
}

// ---------------- the persistent kernel ----------------
__global__ void __launch_bounds__(TPB, 1) persistent_kernel(
    const float* __restrict__ adj,
    const float* __restrict__ c0,
    const float* __restrict__ b_gates,
    const float* __restrict__ W1, const float* __restrict__ b1,
    const float* __restrict__ W2, const float* __restrict__ b2,
    float* __restrict__ out)
{
    extern __shared__ float smem[];
    unsigned* usm = reinterpret_cast<unsigned*>(smem);
    float* ah = smem + SM_AH;
    float* hs = smem + SM_HS;
    uint4* Wsm = reinterpret_cast<uint4*>(smem + SM_W);

    const int b     = blockIdx.y;
    const int kcCTA = blockIdx.x;
    const int n0    = kcCTA * ROWS;
    const int tid   = threadIdx.x;
    const int lane  = tid & 31;
    const int w     = tid >> 5;
    const int g     = lane >> 2;
    const int tig   = lane & 3;
    const int colb  = 8 * w + 2 * tig;    // this thread's gate-column base

    // ---- prologue ----
    #pragma unroll
    for (int i = tid; i < 5 * 32 * 32; i += TPB) Wsm[i] = d_Wfrag4[i];
    for (int e = tid; e < 16 * 80; e += TPB) ah[e] = 0.0f;

    // c state + gate biases in registers
    float creg[4];
    creg[0] = c0[((size_t)b * Nn + n0 + g) * Hn + colb];
    creg[1] = c0[((size_t)b * Nn + n0 + g) * Hn + colb + 1];
    creg[2] = c0[((size_t)b * Nn + n0 + 8 + g) * Hn + colb];
    creg[3] = c0[((size_t)b * Nn + n0 + 8 + g) * Hn + colb + 1];
    float bgr[4][2];
    #pragma unroll
    for (int q = 0; q < 4; ++q) {
        bgr[q][0] = b_gates[q * 64 + colb];
        bgr[q][1] = b_gates[q * 64 + colb + 1];
    }

    // stage A for t = 0
    {
        float4 av[8];
        stageA_load(adj + (((size_t)b * Sn + 0) * Nn + n0) * Nn, av);
        stageA_store(av, usm);
    }

    for (int t = 0; t < Sn; ++t) {
        const int par = t & 1;

        if (tid < 128) ah[(tid >> 3) * 80 + (tid & 7)] = 0.0f;
        __syncthreads();   // A tile + Wsm(first iter) + ah-zero visible

        // ================= Phase 1 =================
        float acch[6][4];
        #pragma unroll
        for (int q2 = 0; q2 < 6; ++q2)
            #pragma unroll
            for (int i = 0; i < 4; ++i) acch[q2][i] = 0.0f;

        const uint4* fb = d_Ffrag + (size_t)(par * Bn + b) * (KC * 8 * 32) + w * 32 + lane;
        const uint4* xb = d_Xfrag + (size_t)(t * Bn + b) * (KC * 32) + lane;

        uint4 xq[4];
        #pragma unroll
        for (int u = 0; u < 4; ++u) xq[u] = xb[(size_t)(4 * w + u) * 32];

        uint4 q[4], qn[4];
        #pragma unroll
        for (int u = 0; u < 4; ++u) q[u] = fb[(size_t)u * 256];

        for (int kcb = 0; kcb < KC; kcb += 4) {
            const bool pf = (kcb + 4) < KC;
            #pragma unroll
            for (int u = 0; u < 4; ++u)
                if (pf) qn[u] = fb[(size_t)(kcb + 4 + u) * 256];
            #pragma unroll
            for (int u = 0; u < 4; ++u) {
                const int kc = kcb + u;
                const uint4 fh = *(const uint4*)(usm + SM_AHI + (kc * 33 + lane) * 4);
                const uint4 fl = *(const uint4*)(usm + SM_ALO + (kc * 33 + lane) * 4);
                const int p = (u & 1) * 3;
                mma_bf16(acch[p + 0], fh.x, fh.y, fh.z, fh.w, q[u].x, q[u].y);
                mma_bf16(acch[p + 1], fh.x, fh.y, fh.z, fh.w, q[u].z, q[u].w);
                mma_bf16(acch[p + 2], fl.x, fl.y, fl.z, fl.w, q[u].x, q[u].y);
            }
            #pragma unroll
            for (int u = 0; u < 4; ++u) q[u] = qn[u];
        }

        // x pass: warp w covers kc in [4w, 4w+4)
        float accx[3][4];
        #pragma unroll
        for (int p = 0; p < 3; ++p)
            #pragma unroll
            for (int i = 0; i < 4; ++i) accx[p][i] = 0.0f;
        #pragma unroll
        for (int u = 0; u < 4; ++u) {
            const int kc = 4 * w + u;
            const uint4 fh = *(const uint4*)(usm + SM_AHI + (kc * 33 + lane) * 4);
            const uint4 fl = *(const uint4*)(usm + SM_ALO + (kc * 33 + lane) * 4);
            mma_bf16(accx[0], fh.x, fh.y, fh.z, fh.w, xq[u].x, xq[u].y);
            mma_bf16(accx[1], fh.x, fh.y, fh.z, fh.w, xq[u].z, xq[u].w);
            mma_bf16(accx[2], fl.x, fl.y, fl.z, fl.w, xq[u].x, xq[u].y);
        }

        // collapse + store ah
        {
            float sh[4], sx[4];
            #pragma unroll
            for (int i = 0; i < 4; ++i) {
                sh[i] = ((acch[0][i] + acch[1][i]) + (acch[2][i] + acch[3][i])) + (acch[4][i] + acch[5][i]);
                sx[i] = (accx[0][i] + accx[1][i]) + accx[2][i];
            }
            const int cb = 8 + 8 * w;
            *(float2*)&ah[g * 80 + cb + 2 * tig]       = make_float2(sh[0], sh[1]);
            *(float2*)&ah[(g + 8) * 80 + cb + 2 * tig] = make_float2(sh[2], sh[3]);
            atomicAdd(&ah[g * 80 + 2 * tig],           sx[0]);
            atomicAdd(&ah[g * 80 + 2 * tig + 1],       sx[1]);
            atomicAdd(&ah[(g + 8) * 80 + 2 * tig],     sx[2]);
            atomicAdd(&ah[(g + 8) * 80 + 2 * tig + 1], sx[3]);
        }
        __syncthreads();

        // ---- issue next adj tile loads (hidden behind phase 2) ----
        float4 av[8];
        if (t < Sn - 1)
            stageA_load(adj + (((size_t)b * Sn + (t + 1)) * Nn + n0) * Nn, av);

        // ================= Phase 2 =================
        // warp w computes ntiles {w, 8+w, 16+w, 24+w} = cols colb..colb+1 of each gate
        float acc2[2][4][4];
        #pragma unroll
        for (int h2 = 0; h2 < 2; ++h2)
            #pragma unroll
            for (int qg = 0; qg < 4; ++qg)
                #pragma unroll
                for (int i = 0; i < 4; ++i) acc2[h2][qg][i] = 0.0f;

        #pragma unroll
        for (int kk = 0; kk < 5; ++kk) {
            const int k0 = kk * 16;
            float2 p0 = *(const float2*)&ah[g * 80 + k0 + 2 * tig];
            float2 p1 = *(const float2*)&ah[(g + 8) * 80 + k0 + 2 * tig];
            float2 p2 = *(const float2*)&ah[g * 80 + k0 + 8 + 2 * tig];
            float2 p3 = *(const float2*)&ah[(g + 8) * 80 + k0 + 8 + 2 * tig];
            unsigned A0h, A0l, A1h, A1l, A2h, A2l, A3h, A3l;
            bsplit2(p0.x, p0.y, A0h, A0l);
            bsplit2(p1.x, p1.y, A1h, A1l);
            bsplit2(p2.x, p2.y, A2h, A2l);
            bsplit2(p3.x, p3.y, A3h, A3l);
            const int hsel = kk & 1;
            #pragma unroll
            for (int qg = 0; qg < 4; ++qg) {
                uint4 qw = Wsm[(kk * 32 + qg * 8 + w) * 32 + lane];
                mma_bf16(acc2[hsel][qg], A0h, A1h, A2h, A3h, qw.x, qw.y);
                mma_bf16(acc2[hsel][qg], A0h, A1h, A2h, A3h, qw.z, qw.w);
                mma_bf16(acc2[hsel][qg], A0l, A1l, A2l, A3l, qw.x, qw.y);
            }
        }

        // ---- store next adj tile into smem (A region free: phase 1 done grid... CTA-wide) ----
        if (t < Sn - 1)
            stageA_store(av, usm);

        // ================= Gates (registers) =================
        #pragma unroll
        for (int j = 0; j < 4; ++j) {
            float gi = acc2[0][0][j] + acc2[1][0][j] + bgr[0][j & 1];
            float gf = acc2[0][1][j] + acc2[1][1][j] + bgr[1][j & 1];
            float go = acc2[0][2][j] + acc2[1][2][j] + bgr[2][j & 1];
            float gg = acc2[0][3][j] + acc2[1][3][j] + bgr[3][j & 1];
            float i_ = sigmoidf_fast(gi);
            float f_ = sigmoidf_fast(gf);
            float o_ = sigmoidf_fast(go);
            float G  = tanhf_fast(gg);
            float cn = f_ * creg[j] + i_ * G;
            creg[j] = cn;
            int row = g + 8 * (j >> 1);
            hs[row * 64 + colb + (j & 1)] = o_ * tanhf_fast(cn);
        }
        __syncthreads();

        // ---- pack h fragments for next step ----
        {
            int j  = tid >> 5;
            int ln = tid & 31;
            int g2 = ln >> 2, tg = ln & 3;
            int col = j * 8 + g2;
            float v0 = hs[(2 * tg) * 64 + col];
            float v1 = hs[(2 * tg + 1) * 64 + col];
            float v2 = hs[(2 * tg + 8) * 64 + col];
            float v3 = hs[(2 * tg + 9) * 64 + col];
            unsigned b0h, b0l, b1h, b1l;
            bsplit2(v0, v1, b0h, b0l);
            bsplit2(v2, v3, b1h, b1l);
            d_Ffrag[(size_t)((par ^ 1) * Bn + b) * (KC * 8 * 32) + kcCTA * 256 + j * 32 + ln] =
                make_uint4(b0h, b1h, b0l, b1l);
        }
        if (t == Sn - 1 && kcCTA == 0 && tid < Hn)
            d_hfinal[b * Hn + tid] = hs[tid];

        grid_barrier((unsigned)(t + 1));
    }

    // ================= Readout (CTA 0 only) =================
    if (kcCTA == 0 && b == 0) {
        float* hid = smem + SM_AH;
        if (tid < Bn * (Hn / 2)) {
            int bb = tid / (Hn / 2);
            int u  = tid % (Hn / 2);
            float s = b1[u];
            #pragma unroll 8
            for (int k = 0; k < Hn; ++k)
                s += d_hfinal[bb * Hn + k] * W1[k * (Hn / 2) + u];
            hid[bb * (Hn / 2) + u] = fmaxf(s, 0.0f);
        }
        __syncthreads();
        if (tid < Bn * OUTn) {
            int bb = tid / OUTn;
            int o  = tid % OUTn;
            float s = b2[o];
            #pragma unroll
            for (int u = 0; u < Hn / 2; ++u)
                s += hid[bb * (Hn / 2) + u] * W2[u * OUTn + o];
            out[bb * OUTn + o] = s;
        }
    }
}

extern "C" void kernel_launch(void* const* d_in, const int* in_sizes, int n_in,
                              void* d_out, int out_size)
{
    const float* x   = (const float*)d_in[0];
    const float* adj = (const float*)d_in[1];
    const float* h0  = (const float*)d_in[2];
    const float* c0  = (const float*)d_in[3];
    const float* Wx  = (const float*)d_in[4];
    const float* Wh  = (const float*)d_in[5];
    const float* bg  = (const float*)d_in[6];
    const float* W1  = (const float*)d_in[7];
    const float* b1  = (const float*)d_in[8];
    const float* W2  = (const float*)d_in[9];
    const float* b2  = (const float*)d_in[10];
    float* out = (float*)d_out;

    cudaFuncSetAttribute(persistent_kernel,
                         cudaFuncAttributeMaxDynamicSharedMemorySize, SMEM_BYTES);

    init_kernel<<<(Sn * Bn * KC * 32 + 255) / 256, 256>>>(x, h0, Wx, Wh);

    dim3 grid(NTIL, Bn);   // 32 x 4 = 128 CTAs, single wave
    persistent_kernel<<<grid, TPB, SMEM_BYTES>>>(adj, c0, bg, W1, b1, W2, b2, out);
}